// round 6
// baseline (speedup 1.0000x reference)
#include <cuda_runtime.h>
#include <math.h>

// Decoder free-run greedy decode. B=1024, T=64, V=256, LAT=256, H=512, L=2.
// GEMMs via mma.sync.m16n8k8 TF32 with 2-term (hi/lo) split => fp32-quality
// products: acc += hi*hi + hi*lo + lo*hi  (lo*lo ~ 2^-24, dropped).
// Per step: A (GRU0 gh0), B1 (gi1), B2 (GRU1 gh1), C (fc+argmax+onehot).
// __device__ symbols referenced from device code only.

#define Bq   1024
#define Hq   512
#define TH3  1536
#define Vq   256
#define LATq 256
#define Tq   64
#define SP   20          // smem k-pitch (16 data + 4 pad) -> conflict-free frags

// ---------------- device scratch ------------------------------------------
__device__ float g_pre[Bq * TH3];          // latent part of gi0 (+b_ih0)
__device__ float g_gi1[Bq * TH3];          // per-step gi1 (+b_ih1)
__device__ float g_wvT[Vq * TH3];          // w_ih0 vocab cols, [v][gate3H]
__device__ float g_wfcT[Hq * Vq];          // w_fc transposed [k][v]
__device__ float g_h0[2][Bq * Hq];
__device__ float g_h1[2][Bq * Hq];
__device__ int   g_idx[Bq];
// tf32 hi/lo splits of the GEMM weight matrices
__device__ float g_whh0h[TH3 * Hq], g_whh0l[TH3 * Hq];
__device__ float g_wih1h[TH3 * Hq], g_wih1l[TH3 * Hq];
__device__ float g_whh1h[TH3 * Hq], g_whh1l[TH3 * Hq];
__device__ float g_wah[TH3 * LATq], g_wal[TH3 * LATq];  // w_ih0 latent cols

__device__ __forceinline__ float sigmoidf_(float x) {
    return 1.0f / (1.0f + expf(-x));
}
__device__ __forceinline__ unsigned cvt_tf32(float x) {
    unsigned r;
    asm("cvt.rna.tf32.f32 %0, %1;" : "=r"(r) : "f"(x));
    return r;
}
__device__ __forceinline__ void split1(float x, float &h, float &l) {
    unsigned hu = cvt_tf32(x);
    float hf = __uint_as_float(hu);
    h = hf;
    l = __uint_as_float(cvt_tf32(x - hf));
}
__device__ __forceinline__ void mma_tf32(float c[4], const unsigned a[4],
                                         unsigned b0, unsigned b1) {
    asm volatile(
        "mma.sync.aligned.m16n8k8.row.col.f32.tf32.tf32.f32 "
        "{%0,%1,%2,%3}, {%4,%5,%6,%7}, {%8,%9}, {%0,%1,%2,%3};"
        : "+f"(c[0]), "+f"(c[1]), "+f"(c[2]), "+f"(c[3])
        : "r"(a[0]), "r"(a[1]), "r"(a[2]), "r"(a[3]), "r"(b0), "r"(b1));
}
#define FU(x) __float_as_uint(x)

// ---------------- init: zero state + transposes + weight splits -----------
__global__ void __launch_bounds__(256) init_kernel(
    const float* __restrict__ w_ih0, const float* __restrict__ w_fc,
    const float* __restrict__ w_hh0, const float* __restrict__ w_ih1,
    const float* __restrict__ w_hh1)
{
    const int gt = blockIdx.x * 256 + threadIdx.x;     // 0..32767
    float4 z = make_float4(0.f, 0.f, 0.f, 0.f);
    #pragma unroll
    for (int q = 0; q < 4; q++) {
        int i = gt + 32768 * q;
        reinterpret_cast<float4*>(g_h0[0])[i] = z;
        reinterpret_cast<float4*>(g_h1[0])[i] = z;
    }
    if (gt < Bq) g_idx[gt] = -1;
    #pragma unroll
    for (int q = 0; q < 12; q++) {                     // w_ih0 vocab transpose
        int i = gt + 32768 * q;
        int v = i / TH3, g = i - v * TH3;
        g_wvT[i] = w_ih0[g * 512 + 256 + v];
    }
    #pragma unroll
    for (int q = 0; q < 4; q++) {                      // w_fc transpose [k][v]
        int i = gt + 32768 * q;
        int k = i >> 8, v = i & 255;
        g_wfcT[i] = w_fc[v * 512 + k];
    }
    for (int q = 0; q < 24; q++) {                     // splits: 786432 elems
        int i = gt + 32768 * q;
        float h, l;
        split1(w_hh0[i], h, l); g_whh0h[i] = h; g_whh0l[i] = l;
        split1(w_ih1[i], h, l); g_wih1h[i] = h; g_wih1l[i] = l;
        split1(w_hh1[i], h, l); g_whh1h[i] = h; g_whh1l[i] = l;
    }
    for (int q = 0; q < 12; q++) {                     // w_ih0 latent split
        int i = gt + 32768 * q;                        // 393216
        int g = i >> 8, c = i & 255;
        float h, l;
        split1(w_ih0[g * 512 + c], h, l);
        g_wah[i] = h; g_wal[i] = l;                    // [g][c] pitch 256
    }
}

// ---------------- TF32 split GEMM core ------------------------------------
// Block 256 thr = 8 warps. Output tile 64 rows x 192 gate-cols.
// warp = (mw = w&3)*16 rows, nw = w>>2 selects col-half of each gate.
// ntile nt: gate = nt>>2, cols = gate*64 + nw*32 + (nt&3)*8 .. +7
// acc[nt][0..3] = C frag: rows {16mw+g, +8}, cols {.. +2tig, +2tig+1}
__device__ __forceinline__ void tf32_gemm(
    float acc[12][4],
    const float* __restrict__ A, int apitch, int rbase, int ktot,
    const float* __restrict__ Whi, const float* __restrict__ Wlo,
    int wpitch, int hs, float* sm)
{
    float* sWh = sm;              // 192*SP = 3840
    float* sWl = sm + 3840;
    float* sAh = sm + 7680;       // 64*SP = 1280
    float* sAl = sm + 8960;       // end 10240
    const int tid  = threadIdx.x;
    const int lane = tid & 31, warp = tid >> 5;
    const int mw = warp & 3, nw = warp >> 2;
    const int g = lane >> 2, tig = lane & 3;
    const int r0 = 16 * mw + g;

    for (int k0 = 0; k0 < ktot; k0 += 16) {
        __syncthreads();
        // W panel: 192 rows x 16 k (hi+lo)
        #pragma unroll
        for (int s = 0; s < 3; s++) {
            int item = tid + 256 * s;
            int row = item >> 2, kq = item & 3;
            int grow = ((row >> 6) << 9) + hs * 64 + (row & 63);
            float4 vh = *reinterpret_cast<const float4*>(
                &Whi[(size_t)grow * wpitch + k0 + 4 * kq]);
            float4 vl = *reinterpret_cast<const float4*>(
                &Wlo[(size_t)grow * wpitch + k0 + 4 * kq]);
            *reinterpret_cast<float4*>(&sWh[row * SP + 4 * kq]) = vh;
            *reinterpret_cast<float4*>(&sWl[row * SP + 4 * kq]) = vl;
        }
        // A panel: 64 rows x 16 k, split on the fly
        {
            int row = tid >> 2, kq = tid & 3;
            float4 x = *reinterpret_cast<const float4*>(
                &A[(size_t)(rbase + row) * apitch + k0 + 4 * kq]);
            float4 h, l;
            split1(x.x, h.x, l.x); split1(x.y, h.y, l.y);
            split1(x.z, h.z, l.z); split1(x.w, h.w, l.w);
            *reinterpret_cast<float4*>(&sAh[row * SP + 4 * kq]) = h;
            *reinterpret_cast<float4*>(&sAl[row * SP + 4 * kq]) = l;
        }
        __syncthreads();
        #pragma unroll
        for (int k8o = 0; k8o < 16; k8o += 8) {
            unsigned ah[4], al[4];
            ah[0] = FU(sAh[r0 * SP + k8o + tig]);
            ah[1] = FU(sAh[(r0 + 8) * SP + k8o + tig]);
            ah[2] = FU(sAh[r0 * SP + k8o + tig + 4]);
            ah[3] = FU(sAh[(r0 + 8) * SP + k8o + tig + 4]);
            al[0] = FU(sAl[r0 * SP + k8o + tig]);
            al[1] = FU(sAl[(r0 + 8) * SP + k8o + tig]);
            al[2] = FU(sAl[r0 * SP + k8o + tig + 4]);
            al[3] = FU(sAl[(r0 + 8) * SP + k8o + tig + 4]);
            #pragma unroll
            for (int nt = 0; nt < 12; nt++) {
                int scol = ((nt >> 2) << 6) + nw * 32 + (nt & 3) * 8 + g;
                unsigned bh0 = FU(sWh[scol * SP + k8o + tig]);
                unsigned bh1 = FU(sWh[scol * SP + k8o + tig + 4]);
                unsigned bl0 = FU(sWl[scol * SP + k8o + tig]);
                unsigned bl1 = FU(sWl[scol * SP + k8o + tig + 4]);
                mma_tf32(acc[nt], ah, bh0, bh1);
                mma_tf32(acc[nt], ah, bl0, bl1);
                mma_tf32(acc[nt], al, bh0, bh1);
            }
        }
    }
}

// ---------------- gi kernels: out = A @ W^T + bias ------------------------
// MODE 0 (pre): A=latent ext, k=256, W=g_wa*, out=g_pre
// MODE 1 (B1):  A=g_h0[pw],   k=512, W=g_wih1*, out=g_gi1
template <int MODE>
__global__ void __launch_bounds__(256) gi_kernel(
    const float* __restrict__ Aext, const float* __restrict__ bias, int t)
{
    __shared__ __align__(16) float sm[10240];
    const int tid  = threadIdx.x;
    const int lane = tid & 31, warp = tid >> 5;
    const int mw = warp & 3, nw = warp >> 2;
    const int g = lane >> 2, tig = lane & 3;
    const int bb = blockIdx.x;
    const int hs = bb & 7;
    const int rbase = (bb >> 3) * 64;

    float acc[12][4];
    #pragma unroll
    for (int nt = 0; nt < 12; nt++)
        #pragma unroll
        for (int i = 0; i < 4; i++) acc[nt][i] = 0.f;

    const float* A   = (MODE == 0) ? Aext : g_h0[1 - (t & 1)];
    const float* Whi = (MODE == 0) ? g_wah : g_wih1h;
    const float* Wlo = (MODE == 0) ? g_wal : g_wih1l;
    const int kp     = (MODE == 0) ? LATq : Hq;
    float* outb      = (MODE == 0) ? g_pre : g_gi1;

    tf32_gemm(acc, A, kp, rbase, kp, Whi, Wlo, kp, hs, sm);

    const int r0 = rbase + 16 * mw + g;
    #pragma unroll
    for (int nt = 0; nt < 12; nt++) {
        int gate = nt >> 2;
        int gc = gate * 512 + hs * 64 + nw * 32 + (nt & 3) * 8 + 2 * tig;
        float b0 = bias[gc], b1 = bias[gc + 1];
        outb[(size_t)r0 * TH3 + gc]           = acc[nt][0] + b0;
        outb[(size_t)r0 * TH3 + gc + 1]       = acc[nt][1] + b1;
        outb[(size_t)(r0 + 8) * TH3 + gc]     = acc[nt][2] + b0;
        outb[(size_t)(r0 + 8) * TH3 + gc + 1] = acc[nt][3] + b1;
    }
}

// ---------------- stage A: layer-0 GRU (one-hot gather) -------------------
__global__ void __launch_bounds__(256) stepA_kernel(
    const float* __restrict__ b_hh0, int t)
{
    __shared__ __align__(16) float sm[10240];
    const int pr = t & 1, pw = 1 - pr;
    const int tid  = threadIdx.x;
    const int lane = tid & 31, warp = tid >> 5;
    const int mw = warp & 3, nw = warp >> 2;
    const int g = lane >> 2, tig = lane & 3;
    const int bb = blockIdx.x;
    const int hs = bb & 7;
    const int rbase = (bb >> 3) * 64;

    float acc[12][4];
    #pragma unroll
    for (int nt = 0; nt < 12; nt++)
        #pragma unroll
        for (int i = 0; i < 4; i++) acc[nt][i] = 0.f;
    tf32_gemm(acc, g_h0[pr], Hq, rbase, Hq, g_whh0h, g_whh0l, Hq, hs, sm);

    const int rg0 = 16 * mw + g;
    #pragma unroll
    for (int q = 0; q < 4; q++) {
        int hb = hs * 64 + nw * 32 + q * 8 + 2 * tig;
        float bR0 = b_hh0[hb],        bR1 = b_hh0[hb + 1];
        float bZ0 = b_hh0[512 + hb],  bZ1 = b_hh0[512 + hb + 1];
        float bN0 = b_hh0[1024 + hb], bN1 = b_hh0[1024 + hb + 1];
        #pragma unroll
        for (int rr = 0; rr < 2; rr++) {
            int b = rbase + rg0 + 8 * rr;
            int ix = g_idx[b];
            #pragma unroll
            for (int cc = 0; cc < 2; cc++) {
                int hp = hb + cc;
                float ir  = g_pre[(size_t)b * TH3 + hp];
                float iz  = g_pre[(size_t)b * TH3 + 512 + hp];
                float in_ = g_pre[(size_t)b * TH3 + 1024 + hp];
                if (ix >= 0) {
                    ir  += g_wvT[(size_t)ix * TH3 + hp];
                    iz  += g_wvT[(size_t)ix * TH3 + 512 + hp];
                    in_ += g_wvT[(size_t)ix * TH3 + 1024 + hp];
                }
                int ai = 2 * rr + cc;
                float R = sigmoidf_(ir + acc[q][ai]     + (cc ? bR1 : bR0));
                float Z = sigmoidf_(iz + acc[4 + q][ai] + (cc ? bZ1 : bZ0));
                float N = tanhf(in_ + R * (acc[8 + q][ai] + (cc ? bN1 : bN0)));
                float hold = g_h0[pr][(size_t)b * Hq + hp];
                g_h0[pw][(size_t)b * Hq + hp] = (1.f - Z) * N + Z * hold;
            }
        }
    }
}

// ---------------- stage B2: layer-1 GRU -----------------------------------
__global__ void __launch_bounds__(256) stepB2_kernel(
    const float* __restrict__ b_hh1, int t)
{
    __shared__ __align__(16) float sm[10240];
    const int pr = t & 1, pw = 1 - pr;
    const int tid  = threadIdx.x;
    const int lane = tid & 31, warp = tid >> 5;
    const int mw = warp & 3, nw = warp >> 2;
    const int g = lane >> 2, tig = lane & 3;
    const int bb = blockIdx.x;
    const int hs = bb & 7;
    const int rbase = (bb >> 3) * 64;

    float acc[12][4];
    #pragma unroll
    for (int nt = 0; nt < 12; nt++)
        #pragma unroll
        for (int i = 0; i < 4; i++) acc[nt][i] = 0.f;
    tf32_gemm(acc, g_h1[pr], Hq, rbase, Hq, g_whh1h, g_whh1l, Hq, hs, sm);

    const int rg0 = 16 * mw + g;
    #pragma unroll
    for (int q = 0; q < 4; q++) {
        int hb = hs * 64 + nw * 32 + q * 8 + 2 * tig;
        float bR0 = b_hh1[hb],        bR1 = b_hh1[hb + 1];
        float bZ0 = b_hh1[512 + hb],  bZ1 = b_hh1[512 + hb + 1];
        float bN0 = b_hh1[1024 + hb], bN1 = b_hh1[1024 + hb + 1];
        #pragma unroll
        for (int rr = 0; rr < 2; rr++) {
            int b = rbase + rg0 + 8 * rr;
            #pragma unroll
            for (int cc = 0; cc < 2; cc++) {
                int hp = hb + cc;
                float ir  = g_gi1[(size_t)b * TH3 + hp];
                float iz  = g_gi1[(size_t)b * TH3 + 512 + hp];
                float in_ = g_gi1[(size_t)b * TH3 + 1024 + hp];
                int ai = 2 * rr + cc;
                float R = sigmoidf_(ir + acc[q][ai]     + (cc ? bR1 : bR0));
                float Z = sigmoidf_(iz + acc[4 + q][ai] + (cc ? bZ1 : bZ0));
                float N = tanhf(in_ + R * (acc[8 + q][ai] + (cc ? bN1 : bN0)));
                float hold = g_h1[pr][(size_t)b * Hq + hp];
                g_h1[pw][(size_t)b * Hq + hp] = (1.f - Z) * N + Z * hold;
            }
        }
    }
}

// ---------------- stage C: logits + argmax + one-hot ----------------------
__global__ void __launch_bounds__(256) stepC_kernel(
    const float* __restrict__ b_fc, float* __restrict__ out, int t)
{
    __shared__ float sHL[8 * Hq];
    __shared__ float sLOG[8 * Vq];
    __shared__ int   sIDX[8];
    const int pw = 1 - (t & 1);
    const int tid = threadIdx.x;
    const int tx  = tid & 31;
    const int ty  = tid >> 5;
    const int rb  = blockIdx.x * 8;

    #pragma unroll
    for (int q = 0; q < 4; q++) {
        int f4 = tid + 256 * q;
        int r  = f4 >> 7;
        int kq = f4 & 127;
        float4 v = *reinterpret_cast<const float4*>(
            &g_h1[pw][(size_t)(rb + r) * Hq + 4 * kq]);
        *reinterpret_cast<float4*>(&sHL[r * Hq + 4 * kq]) = v;
    }
    __syncthreads();

    float acc[8];
    #pragma unroll
    for (int r = 0; r < 8; r++) acc[r] = 0.f;
    #pragma unroll 8
    for (int k = 0; k < Hq; k++) {
        float wv = g_wfcT[k * Vq + tid];
        #pragma unroll
        for (int r = 0; r < 8; r++) acc[r] += sHL[r * Hq + k] * wv;
    }
    float bf = b_fc[tid];
    #pragma unroll
    for (int r = 0; r < 8; r++) sLOG[r * Vq + tid] = acc[r] + bf;
    __syncthreads();

    {   // warp ty reduces row ty, first-max tie-break (matches jnp.argmax)
        int row = ty;
        float bv = -3.4e38f;
        int   bi = 0;
        #pragma unroll
        for (int m = 0; m < 8; m++) {
            int idx = tx + 32 * m;
            float v = sLOG[row * Vq + idx];
            if (v > bv) { bv = v; bi = idx; }
        }
        #pragma unroll
        for (int off = 16; off > 0; off >>= 1) {
            float ov = __shfl_down_sync(0xffffffffu, bv, off);
            int   oi = __shfl_down_sync(0xffffffffu, bi, off);
            if (ov > bv || (ov == bv && oi < bi)) { bv = ov; bi = oi; }
        }
        if (tx == 0) sIDX[row] = bi;
    }
    __syncthreads();
    #pragma unroll
    for (int r = 0; r < 8; r++) {
        out[(size_t)(rb + r) * (Tq * Vq) + t * Vq + tid] =
            (tid == sIDX[r]) ? 1.0f : 0.0f;
    }
    if (tid < 8) g_idx[rb + tid] = sIDX[tid];
}

// ---------------- launch ---------------------------------------------------
extern "C" void kernel_launch(void* const* d_in, const int* in_sizes, int n_in,
                              void* d_out, int out_size)
{
    const float* latent = (const float*)d_in[0];
    // d_in[1] enthalpy: unused on freerun path
    const float* w_ih0  = (const float*)d_in[2];
    const float* w_hh0  = (const float*)d_in[3];
    const float* b_ih0  = (const float*)d_in[4];
    const float* b_hh0  = (const float*)d_in[5];
    const float* w_ih1  = (const float*)d_in[6];
    const float* w_hh1  = (const float*)d_in[7];
    const float* b_ih1  = (const float*)d_in[8];
    const float* b_hh1  = (const float*)d_in[9];
    const float* w_fc   = (const float*)d_in[10];
    const float* b_fc   = (const float*)d_in[11];
    float* out = (float*)d_out;

    init_kernel<<<128, 256>>>(w_ih0, w_fc, w_hh0, w_ih1, w_hh1);
    gi_kernel<0><<<128, 256>>>(latent, b_ih0, 0);          // -> g_pre
    for (int t = 0; t < Tq; t++) {
        stepA_kernel<<<128, 256>>>(b_hh0, t);
        gi_kernel<1><<<128, 256>>>(nullptr, b_ih1, t);     // -> g_gi1
        stepB2_kernel<<<128, 256>>>(b_hh1, t);
        stepC_kernel<<<128, 256>>>(b_fc, out, t);
    }
}

// round 7
// speedup vs baseline: 1.0741x; 1.0741x over previous
#include <cuda_runtime.h>
#include <math.h>

// Decoder free-run greedy decode. B=1024, T=64, V=256, LAT=256, H=512, L=2.
// GEMMs via mma.sync.m16n8k8 TF32, 2-term hi/lo split (fp32-quality):
//   acc += hi*hi + hi*lo + lo*hi.
// R7: grid 256 (2 blocks/SM), block tile 64rows x 96cols, warp tile 32x24.
// __device__ symbols referenced from device code only.

#define Bq   1024
#define Hq   512
#define TH3  1536
#define Vq   256
#define LATq 256
#define Tq   64
#define SP   20          // smem k-pitch: conflict-free scalar frag loads

// ---------------- device scratch ------------------------------------------
__device__ float g_pre[Bq * TH3];
__device__ float g_gi1[Bq * TH3];
__device__ float g_wvT[Vq * TH3];          // w_ih0 vocab cols, [v][gate3H]
__device__ float g_wfcT[Hq * Vq];          // w_fc transposed [k][v]
__device__ float g_h0[2][Bq * Hq];
__device__ float g_h1[2][Bq * Hq];
__device__ int   g_idx[Bq];
// tf32 hi/lo splits of the GEMM weights
__device__ float g_whh0h[TH3 * Hq], g_whh0l[TH3 * Hq];
__device__ float g_wih1h[TH3 * Hq], g_wih1l[TH3 * Hq];
__device__ float g_whh1h[TH3 * Hq], g_whh1l[TH3 * Hq];
__device__ float g_wah[TH3 * LATq], g_wal[TH3 * LATq];

__device__ __forceinline__ float sigmoidf_(float x) {
    return 1.0f / (1.0f + expf(-x));
}
__device__ __forceinline__ unsigned cvt_tf32(float x) {
    unsigned r;
    asm("cvt.rna.tf32.f32 %0, %1;" : "=r"(r) : "f"(x));
    return r;
}
__device__ __forceinline__ void split1(float x, float &h, float &l) {
    float hf = __uint_as_float(cvt_tf32(x));
    h = hf;
    l = __uint_as_float(cvt_tf32(x - hf));
}
__device__ __forceinline__ void mma_tf32(float c[4], const unsigned a[4],
                                         unsigned b0, unsigned b1) {
    asm volatile(
        "mma.sync.aligned.m16n8k8.row.col.f32.tf32.tf32.f32 "
        "{%0,%1,%2,%3}, {%4,%5,%6,%7}, {%8,%9}, {%0,%1,%2,%3};"
        : "+f"(c[0]), "+f"(c[1]), "+f"(c[2]), "+f"(c[3])
        : "r"(a[0]), "r"(a[1]), "r"(a[2]), "r"(a[3]), "r"(b0), "r"(b1));
}
#define FU(x) __float_as_uint(x)

// ---------------- init ----------------------------------------------------
__global__ void __launch_bounds__(256) init_kernel(
    const float* __restrict__ w_ih0, const float* __restrict__ w_fc,
    const float* __restrict__ w_hh0, const float* __restrict__ w_ih1,
    const float* __restrict__ w_hh1)
{
    const int gt = blockIdx.x * 256 + threadIdx.x;     // 0..32767
    float4 z = make_float4(0.f, 0.f, 0.f, 0.f);
    #pragma unroll
    for (int q = 0; q < 4; q++) {
        int i = gt + 32768 * q;
        reinterpret_cast<float4*>(g_h0[0])[i] = z;
        reinterpret_cast<float4*>(g_h1[0])[i] = z;
    }
    if (gt < Bq) g_idx[gt] = -1;
    #pragma unroll
    for (int q = 0; q < 12; q++) {
        int i = gt + 32768 * q;
        int v = i / TH3, g = i - v * TH3;
        g_wvT[i] = w_ih0[g * 512 + 256 + v];
    }
    #pragma unroll
    for (int q = 0; q < 4; q++) {
        int i = gt + 32768 * q;
        int k = i >> 8, v = i & 255;
        g_wfcT[i] = w_fc[v * 512 + k];
    }
    for (int q = 0; q < 24; q++) {                     // 786432 elems
        int i = gt + 32768 * q;
        float h, l;
        split1(w_hh0[i], h, l); g_whh0h[i] = h; g_whh0l[i] = l;
        split1(w_ih1[i], h, l); g_wih1h[i] = h; g_wih1l[i] = l;
        split1(w_hh1[i], h, l); g_whh1h[i] = h; g_whh1l[i] = l;
    }
    for (int q = 0; q < 12; q++) {                     // w_ih0 latent split
        int i = gt + 32768 * q;
        int g = i >> 8, c = i & 255;
        float h, l;
        split1(w_ih0[g * 512 + c], h, l);
        g_wah[i] = h; g_wal[i] = l;                    // [g][c] pitch 256
    }
}

// ---------------- TF32 split GEMM core ------------------------------------
// Block tile: 64 rows x 96 cols (cs picks 32 cols per gate).
// 8 warps: mw = warp&1 (32-row half), nw = warp>>1 (8-col subtile per gate).
// acc[nt(gate)][mt][frag]; thread frag rows {g, g+8}, cols {2tig, 2tig+1}.
__device__ __forceinline__ void tf32_gemm(
    float acc[3][2][4],
    const float* __restrict__ A, int apitch, int rbase, int ktot,
    const float* __restrict__ Whi, const float* __restrict__ Wlo,
    int wpitch, int cs, float* sm)
{
    float* sWh = sm;              // 96*SP = 1920
    float* sWl = sm + 1920;
    float* sAh = sm + 3840;       // 64*SP = 1280
    float* sAl = sm + 5120;       // end 6400
    const int tid  = threadIdx.x;
    const int lane = tid & 31, warp = tid >> 5;
    const int mw = warp & 1, nw = warp >> 1;
    const int g = lane >> 2, tig = lane & 3;

    for (int k0 = 0; k0 < ktot; k0 += 16) {
        __syncthreads();
        // W panel: 96 scols x 16 k, hi then lo (768 float4, 3/thread)
        #pragma unroll
        for (int s = 0; s < 3; s++) {
            int item = tid + 256 * s;          // 0..767
            int half = item >= 384;
            int it2  = item - 384 * half;      // 0..383
            int scol = it2 >> 2, kq = it2 & 3; // scol = gate*32 + c
            int grow = ((scol >> 5) << 9) + cs * 32 + (scol & 31);
            const float* src = half ? Wlo : Whi;
            float* dst = half ? sWl : sWh;
            float4 v = *reinterpret_cast<const float4*>(
                &src[(size_t)grow * wpitch + k0 + 4 * kq]);
            *reinterpret_cast<float4*>(&dst[scol * SP + 4 * kq]) = v;
        }
        // A panel: 64 rows x 16 k, split on the fly (256 float4, 1/thread)
        {
            int row = tid >> 2, kq = tid & 3;
            float4 x = *reinterpret_cast<const float4*>(
                &A[(size_t)(rbase + row) * apitch + k0 + 4 * kq]);
            float4 h, l;
            split1(x.x, h.x, l.x); split1(x.y, h.y, l.y);
            split1(x.z, h.z, l.z); split1(x.w, h.w, l.w);
            *reinterpret_cast<float4*>(&sAh[row * SP + 4 * kq]) = h;
            *reinterpret_cast<float4*>(&sAl[row * SP + 4 * kq]) = l;
        }
        __syncthreads();
        #pragma unroll
        for (int k8o = 0; k8o < 16; k8o += 8) {
            unsigned ah[2][4], al[2][4];
            #pragma unroll
            for (int mt = 0; mt < 2; mt++) {
                int r0 = 32 * mw + 16 * mt + g;
                ah[mt][0] = FU(sAh[r0 * SP + k8o + tig]);
                ah[mt][1] = FU(sAh[(r0 + 8) * SP + k8o + tig]);
                ah[mt][2] = FU(sAh[r0 * SP + k8o + tig + 4]);
                ah[mt][3] = FU(sAh[(r0 + 8) * SP + k8o + tig + 4]);
                al[mt][0] = FU(sAl[r0 * SP + k8o + tig]);
                al[mt][1] = FU(sAl[(r0 + 8) * SP + k8o + tig]);
                al[mt][2] = FU(sAl[r0 * SP + k8o + tig + 4]);
                al[mt][3] = FU(sAl[(r0 + 8) * SP + k8o + tig + 4]);
            }
            #pragma unroll
            for (int nt = 0; nt < 3; nt++) {
                int scol = nt * 32 + nw * 8 + g;
                unsigned bh0 = FU(sWh[scol * SP + k8o + tig]);
                unsigned bh1 = FU(sWh[scol * SP + k8o + tig + 4]);
                unsigned bl0 = FU(sWl[scol * SP + k8o + tig]);
                unsigned bl1 = FU(sWl[scol * SP + k8o + tig + 4]);
                #pragma unroll
                for (int mt = 0; mt < 2; mt++) {
                    mma_tf32(acc[nt][mt], ah[mt], bh0, bh1);
                    mma_tf32(acc[nt][mt], ah[mt], bl0, bl1);
                    mma_tf32(acc[nt][mt], al[mt], bh0, bh1);
                }
            }
        }
    }
}

// ---------------- gi kernels: out = A @ W^T + bias ------------------------
template <int MODE>   // 0: pre (latent, k=256) -> g_pre ; 1: gi1 -> g_gi1
__global__ void __launch_bounds__(256) gi_kernel(
    const float* __restrict__ Aext, const float* __restrict__ bias, int t)
{
    __shared__ __align__(16) float sm[6400];
    const int tid  = threadIdx.x;
    const int lane = tid & 31, warp = tid >> 5;
    const int mw = warp & 1, nw = warp >> 1;
    const int g = lane >> 2, tig = lane & 3;
    const int bb = blockIdx.x;
    const int cs = bb & 15;
    const int rbase = (bb >> 4) * 64;

    float acc[3][2][4];
    #pragma unroll
    for (int nt = 0; nt < 3; nt++)
        #pragma unroll
        for (int mt = 0; mt < 2; mt++)
            #pragma unroll
            for (int i = 0; i < 4; i++) acc[nt][mt][i] = 0.f;

    const float* A   = (MODE == 0) ? Aext : g_h0[1 - (t & 1)];
    const float* Whi = (MODE == 0) ? g_wah : g_wih1h;
    const float* Wlo = (MODE == 0) ? g_wal : g_wih1l;
    const int kp     = (MODE == 0) ? LATq : Hq;
    float* outb      = (MODE == 0) ? g_pre : g_gi1;

    tf32_gemm(acc, A, kp, rbase, kp, Whi, Wlo, kp, cs, sm);

    #pragma unroll
    for (int nt = 0; nt < 3; nt++) {
        int gc = nt * 512 + cs * 32 + nw * 8 + 2 * tig;
        float b0 = bias[gc], b1 = bias[gc + 1];
        #pragma unroll
        for (int mt = 0; mt < 2; mt++) {
            int r0 = rbase + 32 * mw + 16 * mt + g;
            outb[(size_t)r0 * TH3 + gc]           = acc[nt][mt][0] + b0;
            outb[(size_t)r0 * TH3 + gc + 1]       = acc[nt][mt][1] + b1;
            outb[(size_t)(r0 + 8) * TH3 + gc]     = acc[nt][mt][2] + b0;
            outb[(size_t)(r0 + 8) * TH3 + gc + 1] = acc[nt][mt][3] + b1;
        }
    }
}

// ---------------- stage A: layer-0 GRU (one-hot gather) -------------------
__global__ void __launch_bounds__(256) stepA_kernel(
    const float* __restrict__ b_hh0, int t)
{
    __shared__ __align__(16) float sm[6400];
    const int pr = t & 1, pw = 1 - pr;
    const int tid  = threadIdx.x;
    const int lane = tid & 31, warp = tid >> 5;
    const int mw = warp & 1, nw = warp >> 1;
    const int g = lane >> 2, tig = lane & 3;
    const int bb = blockIdx.x;
    const int cs = bb & 15;
    const int rbase = (bb >> 4) * 64;

    float acc[3][2][4];
    #pragma unroll
    for (int nt = 0; nt < 3; nt++)
        #pragma unroll
        for (int mt = 0; mt < 2; mt++)
            #pragma unroll
            for (int i = 0; i < 4; i++) acc[nt][mt][i] = 0.f;
    tf32_gemm(acc, g_h0[pr], Hq, rbase, Hq, g_whh0h, g_whh0l, Hq, cs, sm);

    const int hb = cs * 32 + nw * 8 + 2 * tig;         // hidden col base
    float bR0 = b_hh0[hb],        bR1 = b_hh0[hb + 1];
    float bZ0 = b_hh0[512 + hb],  bZ1 = b_hh0[512 + hb + 1];
    float bN0 = b_hh0[1024 + hb], bN1 = b_hh0[1024 + hb + 1];
    #pragma unroll
    for (int mt = 0; mt < 2; mt++) {
        #pragma unroll
        for (int rr = 0; rr < 2; rr++) {
            int b = rbase + 32 * mw + 16 * mt + g + 8 * rr;
            int ix = g_idx[b];
            #pragma unroll
            for (int cc = 0; cc < 2; cc++) {
                int hp = hb + cc;
                float ir  = g_pre[(size_t)b * TH3 + hp];
                float iz  = g_pre[(size_t)b * TH3 + 512 + hp];
                float in_ = g_pre[(size_t)b * TH3 + 1024 + hp];
                if (ix >= 0) {
                    ir  += g_wvT[(size_t)ix * TH3 + hp];
                    iz  += g_wvT[(size_t)ix * TH3 + 512 + hp];
                    in_ += g_wvT[(size_t)ix * TH3 + 1024 + hp];
                }
                int ai = 2 * rr + cc;
                float R = sigmoidf_(ir + acc[0][mt][ai] + (cc ? bR1 : bR0));
                float Z = sigmoidf_(iz + acc[1][mt][ai] + (cc ? bZ1 : bZ0));
                float N = tanhf(in_ + R * (acc[2][mt][ai] + (cc ? bN1 : bN0)));
                float hold = g_h0[pr][(size_t)b * Hq + hp];
                g_h0[pw][(size_t)b * Hq + hp] = (1.f - Z) * N + Z * hold;
            }
        }
    }
}

// ---------------- stage B2: layer-1 GRU -----------------------------------
__global__ void __launch_bounds__(256) stepB2_kernel(
    const float* __restrict__ b_hh1, int t)
{
    __shared__ __align__(16) float sm[6400];
    const int pr = t & 1, pw = 1 - pr;
    const int tid  = threadIdx.x;
    const int lane = tid & 31, warp = tid >> 5;
    const int mw = warp & 1, nw = warp >> 1;
    const int g = lane >> 2, tig = lane & 3;
    const int bb = blockIdx.x;
    const int cs = bb & 15;
    const int rbase = (bb >> 4) * 64;

    float acc[3][2][4];
    #pragma unroll
    for (int nt = 0; nt < 3; nt++)
        #pragma unroll
        for (int mt = 0; mt < 2; mt++)
            #pragma unroll
            for (int i = 0; i < 4; i++) acc[nt][mt][i] = 0.f;
    tf32_gemm(acc, g_h1[pr], Hq, rbase, Hq, g_whh1h, g_whh1l, Hq, cs, sm);

    const int hb = cs * 32 + nw * 8 + 2 * tig;
    float bR0 = b_hh1[hb],        bR1 = b_hh1[hb + 1];
    float bZ0 = b_hh1[512 + hb],  bZ1 = b_hh1[512 + hb + 1];
    float bN0 = b_hh1[1024 + hb], bN1 = b_hh1[1024 + hb + 1];
    #pragma unroll
    for (int mt = 0; mt < 2; mt++) {
        #pragma unroll
        for (int rr = 0; rr < 2; rr++) {
            int b = rbase + 32 * mw + 16 * mt + g + 8 * rr;
            #pragma unroll
            for (int cc = 0; cc < 2; cc++) {
                int hp = hb + cc;
                float ir  = g_gi1[(size_t)b * TH3 + hp];
                float iz  = g_gi1[(size_t)b * TH3 + 512 + hp];
                float in_ = g_gi1[(size_t)b * TH3 + 1024 + hp];
                int ai = 2 * rr + cc;
                float R = sigmoidf_(ir + acc[0][mt][ai] + (cc ? bR1 : bR0));
                float Z = sigmoidf_(iz + acc[1][mt][ai] + (cc ? bZ1 : bZ0));
                float N = tanhf(in_ + R * (acc[2][mt][ai] + (cc ? bN1 : bN0)));
                float hold = g_h1[pr][(size_t)b * Hq + hp];
                g_h1[pw][(size_t)b * Hq + hp] = (1.f - Z) * N + Z * hold;
            }
        }
    }
}

// ---------------- stage C: logits + argmax + one-hot ----------------------
__global__ void __launch_bounds__(256) stepC_kernel(
    const float* __restrict__ b_fc, float* __restrict__ out, int t)
{
    __shared__ float sHL[8 * Hq];
    __shared__ float sLOG[8 * Vq];
    __shared__ int   sIDX[8];
    const int pw = 1 - (t & 1);
    const int tid = threadIdx.x;
    const int tx  = tid & 31;
    const int ty  = tid >> 5;
    const int rb  = blockIdx.x * 8;

    #pragma unroll
    for (int q = 0; q < 4; q++) {
        int f4 = tid + 256 * q;
        int r  = f4 >> 7;
        int kq = f4 & 127;
        float4 v = *reinterpret_cast<const float4*>(
            &g_h1[pw][(size_t)(rb + r) * Hq + 4 * kq]);
        *reinterpret_cast<float4*>(&sHL[r * Hq + 4 * kq]) = v;
    }
    __syncthreads();

    float acc[8];
    #pragma unroll
    for (int r = 0; r < 8; r++) acc[r] = 0.f;
    #pragma unroll 8
    for (int k = 0; k < Hq; k++) {
        float wv = g_wfcT[k * Vq + tid];
        #pragma unroll
        for (int r = 0; r < 8; r++) acc[r] += sHL[r * Hq + k] * wv;
    }
    float bf = b_fc[tid];
    #pragma unroll
    for (int r = 0; r < 8; r++) sLOG[r * Vq + tid] = acc[r] + bf;
    __syncthreads();

    {   // warp ty reduces row ty, first-max tie-break (matches jnp.argmax)
        int row = ty;
        float bv = -3.4e38f;
        int   bi = 0;
        #pragma unroll
        for (int m = 0; m < 8; m++) {
            int idx = tx + 32 * m;
            float v = sLOG[row * Vq + idx];
            if (v > bv) { bv = v; bi = idx; }
        }
        #pragma unroll
        for (int off = 16; off > 0; off >>= 1) {
            float ov = __shfl_down_sync(0xffffffffu, bv, off);
            int   oi = __shfl_down_sync(0xffffffffu, bi, off);
            if (ov > bv || (ov == bv && oi < bi)) { bv = ov; bi = oi; }
        }
        if (tx == 0) sIDX[row] = bi;
    }
    __syncthreads();
    #pragma unroll
    for (int r = 0; r < 8; r++) {
        out[(size_t)(rb + r) * (Tq * Vq) + t * Vq + tid] =
            (tid == sIDX[r]) ? 1.0f : 0.0f;
    }
    if (tid < 8) g_idx[rb + tid] = sIDX[tid];
}

// ---------------- launch ---------------------------------------------------
extern "C" void kernel_launch(void* const* d_in, const int* in_sizes, int n_in,
                              void* d_out, int out_size)
{
    const float* latent = (const float*)d_in[0];
    // d_in[1] enthalpy: unused on freerun path
    const float* w_ih0  = (const float*)d_in[2];
    const float* w_hh0  = (const float*)d_in[3];
    const float* b_ih0  = (const float*)d_in[4];
    const float* b_hh0  = (const float*)d_in[5];
    const float* w_ih1  = (const float*)d_in[6];
    const float* w_hh1  = (const float*)d_in[7];
    const float* b_ih1  = (const float*)d_in[8];
    const float* b_hh1  = (const float*)d_in[9];
    const float* w_fc   = (const float*)d_in[10];
    const float* b_fc   = (const float*)d_in[11];
    float* out = (float*)d_out;

    init_kernel<<<128, 256>>>(w_ih0, w_fc, w_hh0, w_ih1, w_hh1);
    gi_kernel<0><<<256, 256>>>(latent, b_ih0, 0);          // -> g_pre
    for (int t = 0; t < Tq; t++) {
        stepA_kernel<<<256, 256>>>(b_hh0, t);
        gi_kernel<1><<<256, 256>>>(nullptr, b_ih1, t);     // -> g_gi1
        stepB2_kernel<<<256, 256>>>(b_hh1, t);
        stepC_kernel<<<128, 256>>>(b_fc, out, t);
    }
}

// round 9
// speedup vs baseline: 1.0750x; 1.0009x over previous
#include <cuda_runtime.h>
#include <math.h>

// Decoder free-run greedy decode. B=1024, T=64, V=256, LAT=256, H=512, L=2.
// GEMMs: mma.sync.m16n8k8 TF32, 2-term hi/lo split (fp32-quality):
//   acc += hi*hi + hi*lo + lo*hi.
// R8 (resubmit): software-pipelined panels (reg prefetch), pre-split h-state,
// fused stage B (gi1+gh1 in one kernel). __device__ symbols device-side only.

#define Bq   1024
#define Hq   512
#define TH3  1536
#define Vq   256
#define LATq 256
#define Tq   64
#define SP   20          // smem k-pitch: r*20 mod 32 distinct for 8 rows

// ---------------- device scratch ------------------------------------------
__device__ float g_pre[Bq * TH3];          // latent part of gi0 (+b_ih0)
__device__ float g_wvT[Vq * TH3];          // w_ih0 vocab cols [v][gate3H]
__device__ float g_wfcT[Hq * Vq];          // w_fc transposed [k][v]
__device__ float g_h0f[2][Bq * Hq], g_h0h[2][Bq * Hq], g_h0l[2][Bq * Hq];
__device__ float g_h1f[2][Bq * Hq], g_h1h[2][Bq * Hq], g_h1l[2][Bq * Hq];
__device__ int   g_idx[Bq];
// tf32 hi/lo splits of weights + latent
__device__ float g_whh0h[TH3 * Hq], g_whh0l[TH3 * Hq];
__device__ float g_wih1h[TH3 * Hq], g_wih1l[TH3 * Hq];
__device__ float g_whh1h[TH3 * Hq], g_whh1l[TH3 * Hq];
__device__ float g_wah[TH3 * LATq], g_wal[TH3 * LATq];
__device__ float g_lath[Bq * LATq], g_latl[Bq * LATq];

__device__ __forceinline__ float sigmoidf_(float x) {
    return 1.0f / (1.0f + expf(-x));
}
__device__ __forceinline__ unsigned cvt_tf32(float x) {
    unsigned r;
    asm("cvt.rna.tf32.f32 %0, %1;" : "=r"(r) : "f"(x));
    return r;
}
__device__ __forceinline__ void split1(float x, float &h, float &l) {
    float hf = __uint_as_float(cvt_tf32(x));
    h = hf;
    l = __uint_as_float(cvt_tf32(x - hf));
}
__device__ __forceinline__ void mma_tf32(float c[4], const unsigned a[4],
                                         unsigned b0, unsigned b1) {
    asm volatile(
        "mma.sync.aligned.m16n8k8.row.col.f32.tf32.tf32.f32 "
        "{%0,%1,%2,%3}, {%4,%5,%6,%7}, {%8,%9}, {%0,%1,%2,%3};"
        : "+f"(c[0]), "+f"(c[1]), "+f"(c[2]), "+f"(c[3])
        : "r"(a[0]), "r"(a[1]), "r"(a[2]), "r"(a[3]), "r"(b0), "r"(b1));
}
#define FU(x) __float_as_uint(x)

// ---------------- init ----------------------------------------------------
__global__ void __launch_bounds__(256) init_kernel(
    const float* __restrict__ latent,
    const float* __restrict__ w_ih0, const float* __restrict__ w_fc,
    const float* __restrict__ w_hh0, const float* __restrict__ w_ih1,
    const float* __restrict__ w_hh1)
{
    const int gt = blockIdx.x * 256 + threadIdx.x;     // 0..32767
    float4 z = make_float4(0.f, 0.f, 0.f, 0.f);
    #pragma unroll
    for (int q = 0; q < 4; q++) {                      // zero parity-0 state
        int i = gt + 32768 * q;                        // 131072 float4 each
        reinterpret_cast<float4*>(g_h0f[0])[i] = z;
        reinterpret_cast<float4*>(g_h0h[0])[i] = z;
        reinterpret_cast<float4*>(g_h0l[0])[i] = z;
        reinterpret_cast<float4*>(g_h1f[0])[i] = z;
        reinterpret_cast<float4*>(g_h1h[0])[i] = z;
        reinterpret_cast<float4*>(g_h1l[0])[i] = z;
    }
    if (gt < Bq) g_idx[gt] = -1;
    #pragma unroll
    for (int q = 0; q < 12; q++) {                     // w_ih0 vocab transpose
        int i = gt + 32768 * q;
        int v = i / TH3, g = i - v * TH3;
        g_wvT[i] = w_ih0[g * 512 + 256 + v];
    }
    #pragma unroll
    for (int q = 0; q < 4; q++) {                      // w_fc transpose [k][v]
        int i = gt + 32768 * q;
        int k = i >> 8, v = i & 255;
        g_wfcT[i] = w_fc[v * 512 + k];
    }
    for (int q = 0; q < 24; q++) {                     // weight splits
        int i = gt + 32768 * q;
        float h, l;
        split1(w_hh0[i], h, l); g_whh0h[i] = h; g_whh0l[i] = l;
        split1(w_ih1[i], h, l); g_wih1h[i] = h; g_wih1l[i] = l;
        split1(w_hh1[i], h, l); g_whh1h[i] = h; g_whh1l[i] = l;
    }
    for (int q = 0; q < 12; q++) {                     // w_ih0 latent split
        int i = gt + 32768 * q;
        int g = i >> 8, c = i & 255;
        float h, l;
        split1(w_ih0[g * 512 + c], h, l);
        g_wah[i] = h; g_wal[i] = l;                    // [g][c] pitch 256
    }
    #pragma unroll
    for (int q = 0; q < 8; q++) {                      // latent split
        int i = gt + 32768 * q;                        // 262144 floats
        float h, l;
        split1(latent[i], h, l);
        g_lath[i] = h; g_latl[i] = l;
    }
}

// ---------------- TF32 split GEMM core (register-prefetch pipeline) -------
// Block tile 64 rows x 96 cols; 8 warps: mw=warp&1 (32-row half),
// nw=warp>>1 (8-col subtile per gate). acc[nt(gate)][mt][frag].
// smem: sWh 0..1919, sWl 1920.., sAh 3840.., sAl 5120.. (floats, SP=20).
__device__ __forceinline__ void tf32_gemm(
    float acc[3][2][4],
    const float* __restrict__ Ahi, const float* __restrict__ Alo, int apitch,
    int rbase, int ktot,
    const float* __restrict__ Whi, const float* __restrict__ Wlo, int wpitch,
    int cs, float* sm)
{
    const int tid  = threadIdx.x;
    const int lane = tid & 31, warp = tid >> 5;
    const int mw = warp & 1, nw = warp >> 1;
    const int g = lane >> 2, tig = lane & 3;

    // per-thread panel-load addressing
    const float* wsrc[3];
    int wdst[3];
    #pragma unroll
    for (int s = 0; s < 3; s++) {
        int item = tid + 256 * s;          // 0..767
        int half = item >= 384;
        int it2  = item - 384 * half;
        int scol = it2 >> 2, kq = it2 & 3;
        int grow = ((scol >> 5) << 9) + cs * 32 + (scol & 31);
        wsrc[s] = (half ? Wlo : Whi) + (size_t)grow * wpitch + 4 * kq;
        wdst[s] = half * 1920 + scol * SP + 4 * kq;
    }
    const float* asrc[2];
    int adst[2];
    #pragma unroll
    for (int s = 0; s < 2; s++) {
        int row = tid >> 2, kq = tid & 3;
        asrc[s] = (s ? Alo : Ahi) + (size_t)(rbase + row) * apitch + 4 * kq;
        adst[s] = 3840 + s * 1280 + row * SP + 4 * kq;
    }

    float4 wreg[3], areg[2];
    #pragma unroll
    for (int s = 0; s < 3; s++)
        wreg[s] = *reinterpret_cast<const float4*>(wsrc[s]);
    #pragma unroll
    for (int s = 0; s < 2; s++)
        areg[s] = *reinterpret_cast<const float4*>(asrc[s]);
    __syncthreads();   // previous smem users done
    #pragma unroll
    for (int s = 0; s < 3; s++)
        *reinterpret_cast<float4*>(&sm[wdst[s]]) = wreg[s];
    #pragma unroll
    for (int s = 0; s < 2; s++)
        *reinterpret_cast<float4*>(&sm[adst[s]]) = areg[s];
    __syncthreads();

    float* sWh = sm;
    float* sWl = sm + 1920;
    float* sAh = sm + 3840;
    float* sAl = sm + 5120;

    for (int k0 = 0; k0 < ktot; k0 += 16) {
        const bool more = (k0 + 16) < ktot;
        if (more) {      // prefetch next panel into registers during compute
            #pragma unroll
            for (int s = 0; s < 3; s++)
                wreg[s] = *reinterpret_cast<const float4*>(wsrc[s] + k0 + 16);
            #pragma unroll
            for (int s = 0; s < 2; s++)
                areg[s] = *reinterpret_cast<const float4*>(asrc[s] + k0 + 16);
        }
        #pragma unroll
        for (int k8o = 0; k8o < 16; k8o += 8) {
            unsigned ah[2][4], al[2][4];
            #pragma unroll
            for (int mt = 0; mt < 2; mt++) {
                int r0 = 32 * mw + 16 * mt + g;
                ah[mt][0] = FU(sAh[r0 * SP + k8o + tig]);
                ah[mt][1] = FU(sAh[(r0 + 8) * SP + k8o + tig]);
                ah[mt][2] = FU(sAh[r0 * SP + k8o + tig + 4]);
                ah[mt][3] = FU(sAh[(r0 + 8) * SP + k8o + tig + 4]);
                al[mt][0] = FU(sAl[r0 * SP + k8o + tig]);
                al[mt][1] = FU(sAl[(r0 + 8) * SP + k8o + tig]);
                al[mt][2] = FU(sAl[r0 * SP + k8o + tig + 4]);
                al[mt][3] = FU(sAl[(r0 + 8) * SP + k8o + tig + 4]);
            }
            #pragma unroll
            for (int nt = 0; nt < 3; nt++) {
                int scol = nt * 32 + nw * 8 + g;
                unsigned bh0 = FU(sWh[scol * SP + k8o + tig]);
                unsigned bh1 = FU(sWh[scol * SP + k8o + tig + 4]);
                unsigned bl0 = FU(sWl[scol * SP + k8o + tig]);
                unsigned bl1 = FU(sWl[scol * SP + k8o + tig + 4]);
                #pragma unroll
                for (int mt = 0; mt < 2; mt++) {
                    mma_tf32(acc[nt][mt], ah[mt], bh0, bh1);
                    mma_tf32(acc[nt][mt], ah[mt], bl0, bl1);
                    mma_tf32(acc[nt][mt], al[mt], bh0, bh1);
                }
            }
        }
        __syncthreads();
        if (more) {
            #pragma unroll
            for (int s = 0; s < 3; s++)
                *reinterpret_cast<float4*>(&sm[wdst[s]]) = wreg[s];
            #pragma unroll
            for (int s = 0; s < 2; s++)
                *reinterpret_cast<float4*>(&sm[adst[s]]) = areg[s];
            __syncthreads();
        }
    }
}

#define ACC_ZERO(acc)                                        \
    _Pragma("unroll")                                        \
    for (int nt = 0; nt < 3; nt++)                           \
        _Pragma("unroll")                                    \
        for (int mt = 0; mt < 2; mt++)                       \
            _Pragma("unroll")                                \
            for (int i = 0; i < 4; i++) acc[nt][mt][i] = 0.f;

// ---------------- pre kernel: g_pre = latent @ w_ih0[:, :256]^T + b -------
__global__ void __launch_bounds__(256, 2) pre_kernel(
    const float* __restrict__ bias)
{
    __shared__ __align__(16) float sm[6400];
    const int tid  = threadIdx.x;
    const int lane = tid & 31, warp = tid >> 5;
    const int mw = warp & 1, nw = warp >> 1;
    const int g = lane >> 2, tig = lane & 3;
    const int bb = blockIdx.x;
    const int cs = bb & 15;
    const int rbase = (bb >> 4) * 64;

    float acc[3][2][4];
    ACC_ZERO(acc)
    tf32_gemm(acc, g_lath, g_latl, LATq, rbase, LATq, g_wah, g_wal, LATq,
              cs, sm);

    #pragma unroll
    for (int nt = 0; nt < 3; nt++) {
        int gc = nt * 512 + cs * 32 + nw * 8 + 2 * tig;
        float b0 = bias[gc], b1 = bias[gc + 1];
        #pragma unroll
        for (int mt = 0; mt < 2; mt++) {
            int r0 = rbase + 32 * mw + 16 * mt + g;
            g_pre[(size_t)r0 * TH3 + gc]           = acc[nt][mt][0] + b0;
            g_pre[(size_t)r0 * TH3 + gc + 1]       = acc[nt][mt][1] + b1;
            g_pre[(size_t)(r0 + 8) * TH3 + gc]     = acc[nt][mt][2] + b0;
            g_pre[(size_t)(r0 + 8) * TH3 + gc + 1] = acc[nt][mt][3] + b1;
        }
    }
}

// ---------------- stage A: layer-0 GRU (one-hot gather) -------------------
__global__ void __launch_bounds__(256, 2) stepA_kernel(
    const float* __restrict__ b_hh0, int t)
{
    __shared__ __align__(16) float sm[6400];
    const int pr = t & 1, pw = 1 - pr;
    const int tid  = threadIdx.x;
    const int lane = tid & 31, warp = tid >> 5;
    const int mw = warp & 1, nw = warp >> 1;
    const int g = lane >> 2, tig = lane & 3;
    const int bb = blockIdx.x;
    const int cs = bb & 15;
    const int rbase = (bb >> 4) * 64;

    float acc[3][2][4];
    ACC_ZERO(acc)
    tf32_gemm(acc, g_h0h[pr], g_h0l[pr], Hq, rbase, Hq,
              g_whh0h, g_whh0l, Hq, cs, sm);

    const int hb = cs * 32 + nw * 8 + 2 * tig;
    float bR0 = b_hh0[hb],        bR1 = b_hh0[hb + 1];
    float bZ0 = b_hh0[512 + hb],  bZ1 = b_hh0[512 + hb + 1];
    float bN0 = b_hh0[1024 + hb], bN1 = b_hh0[1024 + hb + 1];
    #pragma unroll
    for (int mt = 0; mt < 2; mt++) {
        #pragma unroll
        for (int rr = 0; rr < 2; rr++) {
            int b = rbase + 32 * mw + 16 * mt + g + 8 * rr;
            int ix = g_idx[b];
            #pragma unroll
            for (int cc = 0; cc < 2; cc++) {
                int hp = hb + cc;
                float ir  = g_pre[(size_t)b * TH3 + hp];
                float iz  = g_pre[(size_t)b * TH3 + 512 + hp];
                float in_ = g_pre[(size_t)b * TH3 + 1024 + hp];
                if (ix >= 0) {
                    ir  += g_wvT[(size_t)ix * TH3 + hp];
                    iz  += g_wvT[(size_t)ix * TH3 + 512 + hp];
                    in_ += g_wvT[(size_t)ix * TH3 + 1024 + hp];
                }
                int ai = 2 * rr + cc;
                float R = sigmoidf_(ir + acc[0][mt][ai] + (cc ? bR1 : bR0));
                float Z = sigmoidf_(iz + acc[1][mt][ai] + (cc ? bZ1 : bZ0));
                float N = tanhf(in_ + R * (acc[2][mt][ai] + (cc ? bN1 : bN0)));
                float hold = g_h0f[pr][(size_t)b * Hq + hp];
                float val = (1.f - Z) * N + Z * hold;
                size_t o = (size_t)b * Hq + hp;
                g_h0f[pw][o] = val;
                float vh, vl;
                split1(val, vh, vl);
                g_h0h[pw][o] = vh;
                g_h0l[pw][o] = vl;
            }
        }
    }
}

// ---------------- stage B: layer-1 GRU, fused gi1 + gh1 -------------------
__global__ void __launch_bounds__(256, 2) stepB_kernel(
    const float* __restrict__ b_ih1, const float* __restrict__ b_hh1, int t)
{
    __shared__ __align__(16) float sm[6400];
    const int pr = t & 1, pw = 1 - pr;
    const int tid  = threadIdx.x;
    const int lane = tid & 31, warp = tid >> 5;
    const int mw = warp & 1, nw = warp >> 1;
    const int g = lane >> 2, tig = lane & 3;
    const int bb = blockIdx.x;
    const int cs = bb & 15;
    const int rbase = (bb >> 4) * 64;

    float ai_[3][2][4], ah_[3][2][4];
    ACC_ZERO(ai_)
    ACC_ZERO(ah_)
    tf32_gemm(ai_, g_h0h[pw], g_h0l[pw], Hq, rbase, Hq,
              g_wih1h, g_wih1l, Hq, cs, sm);
    tf32_gemm(ah_, g_h1h[pr], g_h1l[pr], Hq, rbase, Hq,
              g_whh1h, g_whh1l, Hq, cs, sm);

    const int hb = cs * 32 + nw * 8 + 2 * tig;
    float iR0 = b_ih1[hb],        iR1 = b_ih1[hb + 1];
    float iZ0 = b_ih1[512 + hb],  iZ1 = b_ih1[512 + hb + 1];
    float iN0 = b_ih1[1024 + hb], iN1 = b_ih1[1024 + hb + 1];
    float hR0 = b_hh1[hb],        hR1 = b_hh1[hb + 1];
    float hZ0 = b_hh1[512 + hb],  hZ1 = b_hh1[512 + hb + 1];
    float hN0 = b_hh1[1024 + hb], hN1 = b_hh1[1024 + hb + 1];
    #pragma unroll
    for (int mt = 0; mt < 2; mt++) {
        #pragma unroll
        for (int rr = 0; rr < 2; rr++) {
            int b = rbase + 32 * mw + 16 * mt + g + 8 * rr;
            #pragma unroll
            for (int cc = 0; cc < 2; cc++) {
                int hp = hb + cc;
                int aidx = 2 * rr + cc;
                float R = sigmoidf_(ai_[0][mt][aidx] + (cc ? iR1 : iR0)
                                  + ah_[0][mt][aidx] + (cc ? hR1 : hR0));
                float Z = sigmoidf_(ai_[1][mt][aidx] + (cc ? iZ1 : iZ0)
                                  + ah_[1][mt][aidx] + (cc ? hZ1 : hZ0));
                float N = tanhf(ai_[2][mt][aidx] + (cc ? iN1 : iN0)
                              + R * (ah_[2][mt][aidx] + (cc ? hN1 : hN0)));
                float hold = g_h1f[pr][(size_t)b * Hq + hp];
                float val = (1.f - Z) * N + Z * hold;
                size_t o = (size_t)b * Hq + hp;
                g_h1f[pw][o] = val;
                float vh, vl;
                split1(val, vh, vl);
                g_h1h[pw][o] = vh;
                g_h1l[pw][o] = vl;
            }
        }
    }
}

// ---------------- stage C: logits + argmax + one-hot ----------------------
__global__ void __launch_bounds__(256) stepC_kernel(
    const float* __restrict__ b_fc, float* __restrict__ out, int t)
{
    __shared__ float sHL[8 * Hq];
    __shared__ float sLOG[8 * Vq];
    __shared__ int   sIDX[8];
    const int pw = 1 - (t & 1);
    const int tid = threadIdx.x;
    const int tx  = tid & 31;
    const int ty  = tid >> 5;
    const int rb  = blockIdx.x * 8;

    #pragma unroll
    for (int q = 0; q < 4; q++) {
        int f4 = tid + 256 * q;
        int r  = f4 >> 7;
        int kq = f4 & 127;
        float4 v = *reinterpret_cast<const float4*>(
            &g_h1f[pw][(size_t)(rb + r) * Hq + 4 * kq]);
        *reinterpret_cast<float4*>(&sHL[r * Hq + 4 * kq]) = v;
    }
    __syncthreads();

    float acc[8];
    #pragma unroll
    for (int r = 0; r < 8; r++) acc[r] = 0.f;
    #pragma unroll 8
    for (int k = 0; k < Hq; k++) {
        float wv = g_wfcT[k * Vq + tid];
        #pragma unroll
        for (int r = 0; r < 8; r++) acc[r] += sHL[r * Hq + k] * wv;
    }
    float bf = b_fc[tid];
    #pragma unroll
    for (int r = 0; r < 8; r++) sLOG[r * Vq + tid] = acc[r] + bf;
    __syncthreads();

    {   // warp ty reduces row ty, first-max tie-break (matches jnp.argmax)
        int row = ty;
        float bv = -3.4e38f;
        int   bi = 0;
        #pragma unroll
        for (int m = 0; m < 8; m++) {
            int idx = tx + 32 * m;
            float v = sLOG[row * Vq + idx];
            if (v > bv) { bv = v; bi = idx; }
        }
        #pragma unroll
        for (int off = 16; off > 0; off >>= 1) {
            float ov = __shfl_down_sync(0xffffffffu, bv, off);
            int   oi = __shfl_down_sync(0xffffffffu, bi, off);
            if (ov > bv || (ov == bv && oi < bi)) { bv = ov; bi = oi; }
        }
        if (tx == 0) sIDX[row] = bi;
    }
    __syncthreads();
    #pragma unroll
    for (int r = 0; r < 8; r++) {
        out[(size_t)(rb + r) * (Tq * Vq) + t * Vq + tid] =
            (tid == sIDX[r]) ? 1.0f : 0.0f;
    }
    if (tid < 8) g_idx[rb + tid] = sIDX[tid];
}

// ---------------- launch ---------------------------------------------------
extern "C" void kernel_launch(void* const* d_in, const int* in_sizes, int n_in,
                              void* d_out, int out_size)
{
    const float* latent = (const float*)d_in[0];
    // d_in[1] enthalpy: unused on freerun path
    const float* w_ih0  = (const float*)d_in[2];
    const float* w_hh0  = (const float*)d_in[3];
    const float* b_ih0  = (const float*)d_in[4];
    const float* b_hh0  = (const float*)d_in[5];
    const float* w_ih1  = (const float*)d_in[6];
    const float* w_hh1  = (const float*)d_in[7];
    const float* b_ih1  = (const float*)d_in[8];
    const float* b_hh1  = (const float*)d_in[9];
    const float* w_fc   = (const float*)d_in[10];
    const float* b_fc   = (const float*)d_in[11];
    float* out = (float*)d_out;

    init_kernel<<<128, 256>>>(latent, w_ih0, w_fc, w_hh0, w_ih1, w_hh1);
    pre_kernel<<<256, 256>>>(b_ih0);
    for (int t = 0; t < Tq; t++) {
        stepA_kernel<<<256, 256>>>(b_hh0, t);
        stepB_kernel<<<256, 256>>>(b_ih1, b_hh1, t);
        stepC_kernel<<<128, 256>>>(b_fc, out, t);
    }
}

// round 11
// speedup vs baseline: 1.4883x; 1.3844x over previous
#include <cuda_runtime.h>
#include <cuda_fp16.h>
#include <math.h>

// Decoder free-run greedy decode. B=1024, T=64, V=256, LAT=256, H=512, L=2.
// R11: GRU GEMMs via mma.sync.m16n8k16 FP16 with 2-term split (fp32-quality,
// same 11+11-bit budget as the validated tf32 hi/lo scheme):
//   x = h1+h2 (fp16);  acc += h1*w1 + h1*w2 + h2*w1   (h2*w2 ~ 2^-22 dropped)
// Halves MMA count, fragment LDS, and smem traffic vs the tf32 path.
// pre_kernel keeps the proven tf32 route (runs once). Multi-launch,
// graph-capturable. __device__ symbols referenced from device code only.

#define Bq   1024
#define Hq   512
#define TH3  1536
#define Vq   256
#define LATq 256
#define Tq   64
#define SP   20      // tf32 pre-kernel smem pitch

// ---------------- device scratch ------------------------------------------
__device__ float g_pre[Bq * TH3];
__device__ float g_wvT[Vq * TH3];          // w_ih0 vocab cols [v][gate3H]
__device__ float g_wfcT[Hq * Vq];          // w_fc transposed [k][v]
__device__ float g_h0f[2][Bq * Hq], g_h1f[2][Bq * Hq];
__device__ int   g_idx[Bq];
// fp16 2-term splits: weights [mat: 0=whh0 1=wih1 2=whh1][term]
__device__ __align__(16) __half g_w16[3][2][TH3 * Hq];
__device__ __align__(16) __half g_h0t[2][2][Bq * Hq];   // [parity][term]
__device__ __align__(16) __half g_h1t[2][2][Bq * Hq];
// tf32 split data for pre_kernel
__device__ float g_wah[TH3 * LATq], g_wal[TH3 * LATq];
__device__ float g_lath[Bq * LATq], g_latl[Bq * LATq];

__device__ __forceinline__ float sigmoidf_(float x) {
    return 1.0f / (1.0f + expf(-x));
}
__device__ __forceinline__ unsigned cvt_tf32(float x) {
    unsigned r;
    asm("cvt.rna.tf32.f32 %0, %1;" : "=r"(r) : "f"(x));
    return r;
}
__device__ __forceinline__ void split1(float x, float &h, float &l) {
    float hf = __uint_as_float(cvt_tf32(x));
    h = hf;
    l = __uint_as_float(cvt_tf32(x - hf));
}
__device__ __forceinline__ void split2h(float x, __half &a, __half &b) {
    a = __float2half_rn(x);
    b = __float2half_rn(x - __half2float(a));
}
__device__ __forceinline__ void mma_tf32(float c[4], const unsigned a[4],
                                         unsigned b0, unsigned b1) {
    asm volatile(
        "mma.sync.aligned.m16n8k8.row.col.f32.tf32.tf32.f32 "
        "{%0,%1,%2,%3}, {%4,%5,%6,%7}, {%8,%9}, {%0,%1,%2,%3};"
        : "+f"(c[0]), "+f"(c[1]), "+f"(c[2]), "+f"(c[3])
        : "r"(a[0]), "r"(a[1]), "r"(a[2]), "r"(a[3]), "r"(b0), "r"(b1));
}
__device__ __forceinline__ void mma_f16(float c[4], const unsigned a[4],
                                        unsigned b0, unsigned b1) {
    asm volatile(
        "mma.sync.aligned.m16n8k16.row.col.f32.f16.f16.f32 "
        "{%0,%1,%2,%3}, {%4,%5,%6,%7}, {%8,%9}, {%0,%1,%2,%3};"
        : "+f"(c[0]), "+f"(c[1]), "+f"(c[2]), "+f"(c[3])
        : "r"(a[0]), "r"(a[1]), "r"(a[2]), "r"(a[3]), "r"(b0), "r"(b1));
}
#define FU(x) __float_as_uint(x)

// ---------------- init ----------------------------------------------------
__global__ void __launch_bounds__(256) init_kernel(
    const float* __restrict__ latent,
    const float* __restrict__ w_ih0, const float* __restrict__ w_fc,
    const float* __restrict__ w_hh0, const float* __restrict__ w_ih1,
    const float* __restrict__ w_hh1)
{
    const int gt = blockIdx.x * 256 + threadIdx.x;     // 0..32767
    float4 z = make_float4(0.f, 0.f, 0.f, 0.f);
    #pragma unroll
    for (int q = 0; q < 4; q++) {                      // zero fp32 state p0
        int i = gt + 32768 * q;                        // 131072 float4
        reinterpret_cast<float4*>(g_h0f[0])[i] = z;
        reinterpret_cast<float4*>(g_h1f[0])[i] = z;
    }
    uint4 z4 = make_uint4(0u, 0u, 0u, 0u);
    #pragma unroll
    for (int q = 0; q < 4; q++) {                      // zero fp16 terms p0
        int i = gt + 32768 * q;                        // 131072 uint4 each
        reinterpret_cast<uint4*>(g_h0t[0])[i] = z4;
        reinterpret_cast<uint4*>(g_h1t[0])[i] = z4;
    }
    if (gt < Bq) g_idx[gt] = -1;
    #pragma unroll
    for (int q = 0; q < 12; q++) {                     // w_ih0 vocab transpose
        int i = gt + 32768 * q;
        int v = i / TH3, g = i - v * TH3;
        g_wvT[i] = w_ih0[g * 512 + 256 + v];
    }
    #pragma unroll
    for (int q = 0; q < 4; q++) {                      // w_fc transpose [k][v]
        int i = gt + 32768 * q;
        int k = i >> 8, v = i & 255;
        g_wfcT[i] = w_fc[v * 512 + k];
    }
    for (int q = 0; q < 24; q++) {                     // fp16 weight splits
        int i = gt + 32768 * q;                        // 786432
        __half a, b;
        split2h(w_hh0[i], a, b); g_w16[0][0][i] = a; g_w16[0][1][i] = b;
        split2h(w_ih1[i], a, b); g_w16[1][0][i] = a; g_w16[1][1][i] = b;
        split2h(w_hh1[i], a, b); g_w16[2][0][i] = a; g_w16[2][1][i] = b;
    }
    for (int q = 0; q < 12; q++) {                     // w_ih0 latent tf32
        int i = gt + 32768 * q;
        int g = i >> 8, c = i & 255;
        float h, l;
        split1(w_ih0[g * 512 + c], h, l);
        g_wah[i] = h; g_wal[i] = l;
    }
    #pragma unroll
    for (int q = 0; q < 8; q++) {                      // latent tf32 split
        int i = gt + 32768 * q;
        float h, l;
        split1(latent[i], h, l);
        g_lath[i] = h; g_latl[i] = l;
    }
}

// ---------------- pre kernel (tf32 mma.sync; proven; runs once) -----------
__global__ void __launch_bounds__(256, 2) pre_kernel(
    const float* __restrict__ bias)
{
    __shared__ __align__(16) float sm[6400];
    const int tid  = threadIdx.x;
    const int lane = tid & 31, warp = tid >> 5;
    const int mw = warp & 1, nw = warp >> 1;
    const int g = lane >> 2, tig = lane & 3;
    const int bb = blockIdx.x;
    const int cs = bb & 15;
    const int rbase = (bb >> 4) * 64;

    float acc[3][2][4];
    #pragma unroll
    for (int nt = 0; nt < 3; nt++)
        #pragma unroll
        for (int mt = 0; mt < 2; mt++)
            #pragma unroll
            for (int i = 0; i < 4; i++) acc[nt][mt][i] = 0.f;

    float* sWh = sm;
    float* sWl = sm + 1920;
    float* sAh = sm + 3840;
    float* sAl = sm + 5120;
    for (int k0 = 0; k0 < LATq; k0 += 16) {
        __syncthreads();
        #pragma unroll
        for (int s = 0; s < 3; s++) {
            int item = tid + 256 * s;
            int half_ = item >= 384;
            int it2  = item - 384 * half_;
            int scol = it2 >> 2, kq = it2 & 3;
            int grow = ((scol >> 5) << 9) + cs * 32 + (scol & 31);
            const float* src = half_ ? g_wal : g_wah;
            float* dst = half_ ? sWl : sWh;
            float4 v = *reinterpret_cast<const float4*>(
                &src[(size_t)grow * LATq + k0 + 4 * kq]);
            *reinterpret_cast<float4*>(&dst[scol * SP + 4 * kq]) = v;
        }
        {
            int row = tid >> 2, kq = tid & 3;
            float4 vh = *reinterpret_cast<const float4*>(
                &g_lath[(size_t)(rbase + row) * LATq + k0 + 4 * kq]);
            float4 vl = *reinterpret_cast<const float4*>(
                &g_latl[(size_t)(rbase + row) * LATq + k0 + 4 * kq]);
            *reinterpret_cast<float4*>(&sAh[row * SP + 4 * kq]) = vh;
            *reinterpret_cast<float4*>(&sAl[row * SP + 4 * kq]) = vl;
        }
        __syncthreads();
        #pragma unroll
        for (int k8o = 0; k8o < 16; k8o += 8) {
            unsigned ah[2][4], al[2][4];
            #pragma unroll
            for (int mt = 0; mt < 2; mt++) {
                int r0 = 32 * mw + 16 * mt + g;
                ah[mt][0] = FU(sAh[r0 * SP + k8o + tig]);
                ah[mt][1] = FU(sAh[(r0 + 8) * SP + k8o + tig]);
                ah[mt][2] = FU(sAh[r0 * SP + k8o + tig + 4]);
                ah[mt][3] = FU(sAh[(r0 + 8) * SP + k8o + tig + 4]);
                al[mt][0] = FU(sAl[r0 * SP + k8o + tig]);
                al[mt][1] = FU(sAl[(r0 + 8) * SP + k8o + tig]);
                al[mt][2] = FU(sAl[r0 * SP + k8o + tig + 4]);
                al[mt][3] = FU(sAl[(r0 + 8) * SP + k8o + tig + 4]);
            }
            #pragma unroll
            for (int nt = 0; nt < 3; nt++) {
                int scol = nt * 32 + nw * 8 + g;
                unsigned bh0 = FU(sWh[scol * SP + k8o + tig]);
                unsigned bh1 = FU(sWh[scol * SP + k8o + tig + 4]);
                unsigned bl0 = FU(sWl[scol * SP + k8o + tig]);
                unsigned bl1 = FU(sWl[scol * SP + k8o + tig + 4]);
                #pragma unroll
                for (int mt = 0; mt < 2; mt++) {
                    mma_tf32(acc[nt][mt], ah[mt], bh0, bh1);
                    mma_tf32(acc[nt][mt], ah[mt], bl0, bl1);
                    mma_tf32(acc[nt][mt], al[mt], bh0, bh1);
                }
            }
        }
    }
    #pragma unroll
    for (int nt = 0; nt < 3; nt++) {
        int gc = nt * 512 + cs * 32 + nw * 8 + 2 * tig;
        float b0 = bias[gc], b1 = bias[gc + 1];
        #pragma unroll
        for (int mt = 0; mt < 2; mt++) {
            int r0 = rbase + 32 * mw + 16 * mt + g;
            g_pre[(size_t)r0 * TH3 + gc]           = acc[nt][mt][0] + b0;
            g_pre[(size_t)r0 * TH3 + gc + 1]       = acc[nt][mt][1] + b1;
            g_pre[(size_t)(r0 + 8) * TH3 + gc]     = acc[nt][mt][2] + b0;
            g_pre[(size_t)(r0 + 8) * TH3 + gc + 1] = acc[nt][mt][3] + b1;
        }
    }
}

// ---------------- FP16 2-term GEMM core (register-prefetch pipeline) ------
// Block tile 64 rows x 96 cols. 8 warps: mw=warp&1 (32-row half),
// nw=warp>>1 (8-col subtile per gate). Panels: k16 chunks.
// smem (b32 words): W terms @ term*1152 + scol*12 + w(0..7); A terms @
// 2304 + term*768 + row*12 + w. Pitch 12 words -> conflict-free frag loads.
__device__ __forceinline__ void gemm16(
    float acc[3][2][4],
    const __half* __restrict__ A0, const __half* __restrict__ A1, int apitch,
    int rbase, int ktot,
    const __half* __restrict__ W0, const __half* __restrict__ W1,
    int cs, unsigned* sm)
{
    const int tid  = threadIdx.x;
    const int lane = tid & 31, warp = tid >> 5;
    const int mw = warp & 1, nw = warp >> 1;
    const int g = lane >> 2, tig = lane & 3;

    // combined 16B-granule list: 0..383 = W (2 terms x 96 scols x 2 gran),
    // 384..639 = A (2 terms x 64 rows x 2 gran). 3 slots/thread, slot2
    // valid iff tid < 128.
    const __half* src[3];
    int dstw[3];
    bool vld[3];
    #pragma unroll
    for (int s = 0; s < 3; s++) {
        int i = tid + 256 * s;
        vld[s] = (i < 640);
        int ii = vld[s] ? i : 0;
        if (ii < 384) {
            int term = ii / 192, rem = ii - term * 192;
            int scol = rem >> 1, gr = rem & 1;
            int gcol = ((scol >> 5) << 9) + cs * 32 + (scol & 31);
            src[s]  = (term ? W1 : W0) + (size_t)gcol * Hq + gr * 8;
            dstw[s] = term * 1152 + scol * 12 + gr * 4;
        } else {
            int j = ii - 384;
            int term = j >> 7, rem = j & 127;
            int row = rem >> 1, gr = rem & 1;
            src[s]  = (term ? A1 : A0) + (size_t)(rbase + row) * apitch + gr * 8;
            dstw[s] = 2304 + term * 768 + row * 12 + gr * 4;
        }
    }

    uint4 r[3];
    #pragma unroll
    for (int s = 0; s < 3; s++)
        if (vld[s]) r[s] = *reinterpret_cast<const uint4*>(src[s]);
    __syncthreads();
    #pragma unroll
    for (int s = 0; s < 3; s++)
        if (vld[s]) *reinterpret_cast<uint4*>(&sm[dstw[s]]) = r[s];
    __syncthreads();

    const unsigned* sW = sm;
    const unsigned* sA = sm + 2304;

    for (int k0 = 0; k0 < ktot; k0 += 16) {
        const bool more = (k0 + 16) < ktot;
        if (more) {
            #pragma unroll
            for (int s = 0; s < 3; s++)
                if (vld[s])
                    r[s] = *reinterpret_cast<const uint4*>(src[s] + k0 + 16);
        }
        unsigned a[2][2][4];          // [term][mt][frag]
        #pragma unroll
        for (int term = 0; term < 2; term++)
            #pragma unroll
            for (int mt = 0; mt < 2; mt++) {
                int r0 = 32 * mw + 16 * mt + g;
                int tb = term * 768;
                a[term][mt][0] = sA[tb + r0 * 12 + tig];
                a[term][mt][1] = sA[tb + (r0 + 8) * 12 + tig];
                a[term][mt][2] = sA[tb + r0 * 12 + 4 + tig];
                a[term][mt][3] = sA[tb + (r0 + 8) * 12 + 4 + tig];
            }
        #pragma unroll
        for (int nt = 0; nt < 3; nt++) {
            int scol = nt * 32 + nw * 8 + g;
            unsigned b00 = sW[scol * 12 + tig];
            unsigned b01 = sW[scol * 12 + 4 + tig];
            unsigned b10 = sW[1152 + scol * 12 + tig];
            unsigned b11 = sW[1152 + scol * 12 + 4 + tig];
            #pragma unroll
            for (int mt = 0; mt < 2; mt++) {
                mma_f16(acc[nt][mt], a[0][mt], b00, b01);   // h1*w1
                mma_f16(acc[nt][mt], a[0][mt], b10, b11);   // h1*w2
                mma_f16(acc[nt][mt], a[1][mt], b00, b01);   // h2*w1
            }
        }
        __syncthreads();
        if (more) {
            #pragma unroll
            for (int s = 0; s < 3; s++)
                if (vld[s]) *reinterpret_cast<uint4*>(&sm[dstw[s]]) = r[s];
            __syncthreads();
        }
    }
}

#define ACC_ZERO(acc)                                        \
    _Pragma("unroll")                                        \
    for (int nt = 0; nt < 3; nt++)                           \
        _Pragma("unroll")                                    \
        for (int mt = 0; mt < 2; mt++)                       \
            _Pragma("unroll")                                \
            for (int i = 0; i < 4; i++) acc[nt][mt][i] = 0.f;

// ---------------- stage A: layer-0 GRU (one-hot gather) -------------------
__global__ void __launch_bounds__(256, 2) stepA_kernel(
    const float* __restrict__ b_hh0, int t)
{
    __shared__ __align__(16) unsigned sm[3840];
    const int pr = t & 1, pw = 1 - pr;
    const int tid  = threadIdx.x;
    const int lane = tid & 31, warp = tid >> 5;
    const int mw = warp & 1, nw = warp >> 1;
    const int g = lane >> 2, tig = lane & 3;
    const int bb = blockIdx.x;
    const int cs = bb & 15;
    const int rbase = (bb >> 4) * 64;

    float acc[3][2][4];
    ACC_ZERO(acc)
    gemm16(acc, g_h0t[pr][0], g_h0t[pr][1], Hq, rbase, Hq,
           g_w16[0][0], g_w16[0][1], cs, sm);

    const int hb = cs * 32 + nw * 8 + 2 * tig;
    float bR0 = b_hh0[hb],        bR1 = b_hh0[hb + 1];
    float bZ0 = b_hh0[512 + hb],  bZ1 = b_hh0[512 + hb + 1];
    float bN0 = b_hh0[1024 + hb], bN1 = b_hh0[1024 + hb + 1];
    #pragma unroll
    for (int mt = 0; mt < 2; mt++) {
        #pragma unroll
        for (int rr = 0; rr < 2; rr++) {
            int b = rbase + 32 * mw + 16 * mt + g + 8 * rr;
            int ix = g_idx[b];
            #pragma unroll
            for (int cc = 0; cc < 2; cc++) {
                int hp = hb + cc;
                float ir  = g_pre[(size_t)b * TH3 + hp];
                float iz  = g_pre[(size_t)b * TH3 + 512 + hp];
                float in_ = g_pre[(size_t)b * TH3 + 1024 + hp];
                if (ix >= 0) {
                    ir  += g_wvT[(size_t)ix * TH3 + hp];
                    iz  += g_wvT[(size_t)ix * TH3 + 512 + hp];
                    in_ += g_wvT[(size_t)ix * TH3 + 1024 + hp];
                }
                int ai = 2 * rr + cc;
                float R = sigmoidf_(ir + acc[0][mt][ai] + (cc ? bR1 : bR0));
                float Z = sigmoidf_(iz + acc[1][mt][ai] + (cc ? bZ1 : bZ0));
                float N = tanhf(in_ + R * (acc[2][mt][ai] + (cc ? bN1 : bN0)));
                float hold = g_h0f[pr][(size_t)b * Hq + hp];
                float val = (1.f - Z) * N + Z * hold;
                size_t o = (size_t)b * Hq + hp;
                g_h0f[pw][o] = val;
                __half v1, v2;
                split2h(val, v1, v2);
                g_h0t[pw][0][o] = v1;
                g_h0t[pw][1][o] = v2;
            }
        }
    }
}

// ---------------- stage B: layer-1 GRU, fused gi1 + gh1 -------------------
__global__ void __launch_bounds__(256, 2) stepB_kernel(
    const float* __restrict__ b_ih1, const float* __restrict__ b_hh1, int t)
{
    __shared__ __align__(16) unsigned sm[3840];
    const int pr = t & 1, pw = 1 - pr;
    const int tid  = threadIdx.x;
    const int lane = tid & 31, warp = tid >> 5;
    const int mw = warp & 1, nw = warp >> 1;
    const int g = lane >> 2, tig = lane & 3;
    const int bb = blockIdx.x;
    const int cs = bb & 15;
    const int rbase = (bb >> 4) * 64;

    float ai_[3][2][4], ah_[3][2][4];
    ACC_ZERO(ai_)
    ACC_ZERO(ah_)
    gemm16(ai_, g_h0t[pw][0], g_h0t[pw][1], Hq, rbase, Hq,
           g_w16[1][0], g_w16[1][1], cs, sm);
    gemm16(ah_, g_h1t[pr][0], g_h1t[pr][1], Hq, rbase, Hq,
           g_w16[2][0], g_w16[2][1], cs, sm);

    const int hb = cs * 32 + nw * 8 + 2 * tig;
    float iR0 = b_ih1[hb],        iR1 = b_ih1[hb + 1];
    float iZ0 = b_ih1[512 + hb],  iZ1 = b_ih1[512 + hb + 1];
    float iN0 = b_ih1[1024 + hb], iN1 = b_ih1[1024 + hb + 1];
    float hR0 = b_hh1[hb],        hR1 = b_hh1[hb + 1];
    float hZ0 = b_hh1[512 + hb],  hZ1 = b_hh1[512 + hb + 1];
    float hN0 = b_hh1[1024 + hb], hN1 = b_hh1[1024 + hb + 1];
    #pragma unroll
    for (int mt = 0; mt < 2; mt++) {
        #pragma unroll
        for (int rr = 0; rr < 2; rr++) {
            int b = rbase + 32 * mw + 16 * mt + g + 8 * rr;
            #pragma unroll
            for (int cc = 0; cc < 2; cc++) {
                int hp = hb + cc;
                int aidx = 2 * rr + cc;
                float R = sigmoidf_(ai_[0][mt][aidx] + (cc ? iR1 : iR0)
                                  + ah_[0][mt][aidx] + (cc ? hR1 : hR0));
                float Z = sigmoidf_(ai_[1][mt][aidx] + (cc ? iZ1 : iZ0)
                                  + ah_[1][mt][aidx] + (cc ? hZ1 : hZ0));
                float N = tanhf(ai_[2][mt][aidx] + (cc ? iN1 : iN0)
                              + R * (ah_[2][mt][aidx] + (cc ? hN1 : hN0)));
                float hold = g_h1f[pr][(size_t)b * Hq + hp];
                float val = (1.f - Z) * N + Z * hold;
                size_t o = (size_t)b * Hq + hp;
                g_h1f[pw][o] = val;
                __half v1, v2;
                split2h(val, v1, v2);
                g_h1t[pw][0][o] = v1;
                g_h1t[pw][1][o] = v2;
            }
        }
    }
}

// ---------------- stage C: logits + argmax + one-hot ----------------------
__global__ void __launch_bounds__(256) stepC_kernel(
    const float* __restrict__ b_fc, float* __restrict__ out, int t)
{
    __shared__ float sHL[8 * Hq];
    __shared__ float sLOG[8 * Vq];
    __shared__ int   sIDX[8];
    const int pw = 1 - (t & 1);
    const int tid = threadIdx.x;
    const int tx  = tid & 31;
    const int ty  = tid >> 5;
    const int rb  = blockIdx.x * 8;

    #pragma unroll
    for (int q = 0; q < 4; q++) {
        int f4 = tid + 256 * q;
        int r  = f4 >> 7;
        int kq = f4 & 127;
        float4 v = *reinterpret_cast<const float4*>(
            &g_h1f[pw][(size_t)(rb + r) * Hq + 4 * kq]);
        *reinterpret_cast<float4*>(&sHL[r * Hq + 4 * kq]) = v;
    }
    __syncthreads();

    float acc[8];
    #pragma unroll
    for (int r = 0; r < 8; r++) acc[r] = 0.f;
    #pragma unroll 8
    for (int k = 0; k < Hq; k++) {
        float wv = g_wfcT[k * Vq + tid];
        #pragma unroll
        for (int r = 0; r < 8; r++) acc[r] += sHL[r * Hq + k] * wv;
    }
    float bf = b_fc[tid];
    #pragma unroll
    for (int r = 0; r < 8; r++) sLOG[r * Vq + tid] = acc[r] + bf;
    __syncthreads();

    {   // warp ty reduces row ty, first-max tie-break (matches jnp.argmax)
        int row = ty;
        float bv = -3.4e38f;
        int   bi = 0;
        #pragma unroll
        for (int m = 0; m < 8; m++) {
            int idx = tx + 32 * m;
            float v = sLOG[row * Vq + idx];
            if (v > bv) { bv = v; bi = idx; }
        }
        #pragma unroll
        for (int off = 16; off > 0; off >>= 1) {
            float ov = __shfl_down_sync(0xffffffffu, bv, off);
            int   oi = __shfl_down_sync(0xffffffffu, bi, off);
            if (ov > bv || (ov == bv && oi < bi)) { bv = ov; bi = oi; }
        }
        if (tx == 0) sIDX[row] = bi;
    }
    __syncthreads();
    #pragma unroll
    for (int r = 0; r < 8; r++) {
        out[(size_t)(rb + r) * (Tq * Vq) + t * Vq + tid] =
            (tid == sIDX[r]) ? 1.0f : 0.0f;
    }
    if (tid < 8) g_idx[rb + tid] = sIDX[tid];
}

// ---------------- launch ---------------------------------------------------
extern "C" void kernel_launch(void* const* d_in, const int* in_sizes, int n_in,
                              void* d_out, int out_size)
{
    const float* latent = (const float*)d_in[0];
    // d_in[1] enthalpy: unused on freerun path
    const float* w_ih0  = (const float*)d_in[2];
    const float* w_hh0  = (const float*)d_in[3];
    const float* b_ih0  = (const float*)d_in[4];
    const float* b_hh0  = (const float*)d_in[5];
    const float* w_ih1  = (const float*)d_in[6];
    const float* w_hh1  = (const float*)d_in[7];
    const float* b_ih1  = (const float*)d_in[8];
    const float* b_hh1  = (const float*)d_in[9];
    const float* w_fc   = (const float*)d_in[10];
    const float* b_fc   = (const float*)d_in[11];
    float* out = (float*)d_out;

    init_kernel<<<128, 256>>>(latent, w_ih0, w_fc, w_hh0, w_ih1, w_hh1);
    pre_kernel<<<256, 256>>>(b_ih0);
    for (int t = 0; t < Tq; t++) {
        stepA_kernel<<<256, 256>>>(b_hh0, t);
        stepB_kernel<<<256, 256>>>(b_ih1, b_hh1, t);
        stepC_kernel<<<128, 256>>>(b_fc, out, t);
    }
}